// round 4
// baseline (speedup 1.0000x reference)
#include <cuda_runtime.h>

// ---------------- problem constants (fixed shapes) -------------------------
constexpr int Bn = 4;
constexpr int Nn = 8192;
constexpr int Cc = 32;
constexpr int M2 = 8192;
constexpr int M3 = 4096;
constexpr int M4 = 2048;
constexpr int MM = 4096;

constexpr int QPB   = 64;          // queries per block
constexpr int PARTS = 8;           // candidate-partitions (== warps per block)
constexpr int NT    = 256;         // threads per block
constexpr int TILE  = 512;         // candidates staged per smem tile
constexpr int SLICE = TILE / PARTS;     // 64 candidates per part per tile
constexpr float BIG = 3.0e38f;

// ---------------- device scratch (SoA, no allocations) ---------------------
__device__ float g_v[96];
__device__ float g2x[Bn*M2], g2y[Bn*M2], g2z[Bn*M2], g2w[Bn*M2], g2f[Bn*M2];
__device__ float g3x[Bn*M3], g3y[Bn*M3], g3z[Bn*M3], g3w[Bn*M3], g3f[Bn*M3];
__device__ float g4x[Bn*M4], g4y[Bn*M4], g4z[Bn*M4], g4w[Bn*M4], g4f[Bn*M4];
__device__ float gmx[Bn*MM], gmy[Bn*MM], gmz[Bn*MM], gmw[Bn*MM];

// ---------------- packed f32x2 math ------------------------------------------
union F2U { float2 f; unsigned long long u; };
__device__ __forceinline__ float2 ffma2(float2 a, float2 b, float2 c) {
    F2U A, B, C, R;
    A.f = a; B.f = b; C.f = c;
    asm("fma.rn.f32x2 %0, %1, %2, %3;" : "=l"(R.u) : "l"(A.u), "l"(B.u), "l"(C.u));
    return R.f;
}
__device__ __forceinline__ float2 fadd2(float2 a, float2 b) {
    F2U A, B, R;
    A.f = a; B.f = b;
    asm("add.rn.f32x2 %0, %1, %2;" : "=l"(R.u) : "l"(A.u), "l"(B.u));
    return R.f;
}

// ---------------- tiny precompute kernels ----------------------------------
__global__ void compute_v_kernel(const float* __restrict__ w_fc,
                                 const float* __restrict__ w_cls) {
    int j = threadIdx.x;
    if (j < 96) {
        float acc = 0.f;
#pragma unroll
        for (int k = 0; k < 64; k++) acc = fmaf(w_cls[k], w_fc[k * 96 + j], acc);
        g_v[j] = acc;
    }
}

__global__ void pack_feat_kernel(const float* __restrict__ known,
                                 const float* __restrict__ feats,
                                 int total, int which) {
    int i = blockIdx.x * blockDim.x + threadIdx.x;
    if (i >= total) return;
    float *px, *py, *pz, *pw, *pf; int voff;
    if (which == 0)      { px=g2x; py=g2y; pz=g2z; pw=g2w; pf=g2f; voff = 0;  }
    else if (which == 1) { px=g3x; py=g3y; pz=g3z; pw=g3w; pf=g3f; voff = 32; }
    else                 { px=g4x; py=g4y; pz=g4z; pw=g4w; pf=g4f; voff = 64; }

    float x = known[3 * i + 0];
    float y = known[3 * i + 1];
    float z = known[3 * i + 2];
    // same rounding order as jnp.sum(known*known, -1)
    float kk = __fadd_rn(__fadd_rn(__fmul_rn(x, x), __fmul_rn(y, y)), __fmul_rn(z, z));
    px[i] = x; py[i] = y; pz[i] = z; pw[i] = kk;

    float acc = 0.f;
    const float4* f4 = reinterpret_cast<const float4*>(feats + (size_t)i * Cc);
#pragma unroll
    for (int j = 0; j < 8; j++) {
        float4 t = f4[j];
        acc = fmaf(t.x, g_v[voff + 4 * j + 0], acc);
        acc = fmaf(t.y, g_v[voff + 4 * j + 1], acc);
        acc = fmaf(t.z, g_v[voff + 4 * j + 2], acc);
        acc = fmaf(t.w, g_v[voff + 4 * j + 3], acc);
    }
    pf[i] = acc;
}

__global__ void pack_match_kernel(const float* __restrict__ known, int total) {
    int i = blockIdx.x * blockDim.x + threadIdx.x;
    if (i >= total) return;
    float x = known[3 * i + 0];
    float y = known[3 * i + 1];
    float z = known[3 * i + 2];
    float kk = __fadd_rn(__fadd_rn(__fmul_rn(x, x), __fmul_rn(y, y)), __fmul_rn(z, z));
    gmx[i] = x; gmy[i] = y; gmz[i] = z; gmw[i] = kk;
}

// ---------------- top-3 maintenance ------------------------------------------
__device__ __forceinline__ void try_ins(float e, float fv, float t[3], float f[3]) {
    if (e < t[2]) {
        if (e < t[1]) {
            t[2] = t[1]; f[2] = f[1];
            if (e < t[0]) { t[1] = t[0]; f[1] = f[0]; t[0] = e; f[0] = fv; }
            else          { t[1] = e;    f[1] = fv; }
        } else { t[2] = e; f[2] = fv; }
    }
}

// ---------------- interp-set scan: top-3 of d = (qq+kk) - 2*dot --------------
// d accumulation order matches round-2 / reference: s = qq+kk, then fma x,y,z.
__device__ __forceinline__ void scan_set(
    const float* __restrict__ gx, const float* __restrict__ gy,
    const float* __restrict__ gz, const float* __restrict__ gw,
    const float* __restrict__ gf, int M,
    const float2 c2x[2], const float2 c2y[2], const float2 c2z[2],
    const float2 qq2[2],
    int tid, int part,
    float* s_x, float* s_y, float* s_z, float* s_w, float* s_fv,
    float t[2][3], float f[2][3])
{
#pragma unroll
    for (int j = 0; j < 2; j++) {
        t[j][0] = t[j][1] = t[j][2] = BIG;
        f[j][0] = f[j][1] = f[j][2] = 0.f;
    }
    for (int tb = 0; tb < M; tb += TILE) {
        __syncthreads();
#pragma unroll
        for (int i = tid; i < TILE; i += NT) {
            s_x[i] = gx[tb + i]; s_y[i] = gy[tb + i]; s_z[i] = gz[tb + i];
            s_w[i] = gw[tb + i]; s_fv[i] = gf[tb + i];
        }
        __syncthreads();
        const int base = part * SLICE;
        const float2* x2 = reinterpret_cast<const float2*>(s_x + base);
        const float2* y2 = reinterpret_cast<const float2*>(s_y + base);
        const float2* z2 = reinterpret_cast<const float2*>(s_z + base);
        const float2* w2 = reinterpret_cast<const float2*>(s_w + base);
#pragma unroll 4
        for (int g = 0; g < SLICE / 4; g++) {          // 16 groups of 4 cands
            float2 xl = x2[2*g], xh = x2[2*g+1];
            float2 yl = y2[2*g], yh = y2[2*g+1];
            float2 zl = z2[2*g], zh = z2[2*g+1];
            float2 wl = w2[2*g], wh = w2[2*g+1];
#pragma unroll
            for (int j = 0; j < 2; j++) {
                float2 sl = fadd2(qq2[j], wl);
                float2 sh = fadd2(qq2[j], wh);
                float2 dl = ffma2(c2x[j], xl, sl);
                dl = ffma2(c2y[j], yl, dl);
                dl = ffma2(c2z[j], zl, dl);
                float2 dh = ffma2(c2x[j], xh, sh);
                dh = ffma2(c2y[j], yh, dh);
                dh = ffma2(c2z[j], zh, dh);
                float m = fminf(fminf(dl.x, dl.y), fminf(dh.x, dh.y));
                if (m < t[j][2]) {                     // rare after warm-up
                    int idx = base + 4 * g;
                    try_ins(dl.x, s_fv[idx + 0], t[j], f[j]);
                    try_ins(dl.y, s_fv[idx + 1], t[j], f[j]);
                    try_ins(dh.x, s_fv[idx + 2], t[j], f[j]);
                    try_ins(dh.y, s_fv[idx + 3], t[j], f[j]);
                }
            }
        }
    }
}

// ---------------- mask scan: any(d2 < 0.25), exact-rounding on borderline ---
// fast path may defer qq (binary output protected by 0.0625 margin + recheck)
__device__ __forceinline__ void scan_mask(
    const float* __restrict__ gx, const float* __restrict__ gy,
    const float* __restrict__ gz, const float* __restrict__ gw, int M,
    const float2 c2x[2], const float2 c2y[2], const float2 c2z[2],
    const float qx[2], const float qy[2], const float qz[2], const float qqv[2],
    int tid, int part,
    float* s_x, float* s_y, float* s_z, float* s_w,
    bool found[2])
{
    found[0] = found[1] = false;
    // fast-path threshold: qq + e < 0.25 + margin  <=>  e < 0.3125 - qq
    float tf[2] = { 0.3125f - qqv[0], 0.3125f - qqv[1] };
    for (int tb = 0; tb < M; tb += TILE) {
        __syncthreads();
#pragma unroll
        for (int i = tid; i < TILE; i += NT) {
            s_x[i] = gx[tb + i]; s_y[i] = gy[tb + i];
            s_z[i] = gz[tb + i]; s_w[i] = gw[tb + i];
        }
        __syncthreads();
        const int base = part * SLICE;
        const float2* x2 = reinterpret_cast<const float2*>(s_x + base);
        const float2* y2 = reinterpret_cast<const float2*>(s_y + base);
        const float2* z2 = reinterpret_cast<const float2*>(s_z + base);
        const float2* w2 = reinterpret_cast<const float2*>(s_w + base);
#pragma unroll 4
        for (int g = 0; g < SLICE / 4; g++) {
            float2 xl = x2[2*g], xh = x2[2*g+1];
            float2 yl = y2[2*g], yh = y2[2*g+1];
            float2 zl = z2[2*g], zh = z2[2*g+1];
            float2 wl = w2[2*g], wh = w2[2*g+1];
#pragma unroll
            for (int j = 0; j < 2; j++) {
                float2 el = ffma2(c2x[j], xl, ffma2(c2y[j], yl, ffma2(c2z[j], zl, wl)));
                float2 eh = ffma2(c2x[j], xh, ffma2(c2y[j], yh, ffma2(c2z[j], zh, wh)));
                float m = fminf(fminf(el.x, el.y), fminf(eh.x, eh.y));
                if (m < tf[j]) {                      // extremely rare
                    int idx = base + 4 * g;
#pragma unroll
                    for (int c = 0; c < 4; c++) {
                        float mx = s_x[idx + c], my = s_y[idx + c];
                        float mz = s_z[idx + c], kk = s_w[idx + c];
                        // bit-exact reference-mimic rounding
                        float dot = __fadd_rn(__fadd_rn(__fmul_rn(qx[j], mx),
                                                        __fmul_rn(qy[j], my)),
                                              __fmul_rn(qz[j], mz));
                        float d = __fsub_rn(__fadd_rn(qqv[j], kk),
                                            __fadd_rn(dot, dot));
                        if (d < 0.25f) found[j] = true;
                    }
                }
            }
        }
    }
}

// ---------------- merge 24 partial top-3 entries into the pred contribution -
__device__ __forceinline__ float merge_one(const float2* __restrict__ ent) {
    float t[3] = {BIG, BIG, BIG}, f[3] = {0.f, 0.f, 0.f};
#pragma unroll
    for (int k = 0; k < PARTS * 3; k++) {
        float2 c = ent[k];
        try_ins(c.x, c.y, t, f);
    }
    float d0 = fmaxf(t[0], 0.f);
    float d1 = fmaxf(t[1], 0.f);
    float d2 = fmaxf(t[2], 0.f);
    float r0 = 1.f / (d0 + 1e-8f);
    float r1 = 1.f / (d1 + 1e-8f);
    float r2 = 1.f / (d2 + 1e-8f);
    return fmaf(r0, f[0], fmaf(r1, f[1], r2 * f[2])) / (r0 + r1 + r2);
}

// ---------------- fused main kernel -----------------------------------------
__global__ void __launch_bounds__(NT, 4)
fused_kernel(const float* __restrict__ pts, float* __restrict__ out) {
    __shared__ float  s_x[TILE], s_y[TILE], s_z[TILE], s_w[TILE], s_fv[TILE];
    __shared__ float2 s_m[QPB * PARTS * 3];   // merge entries (12 KB)

    const int tid   = threadIdx.x;
    const int qslot = tid & 31;                // 0..31  (lane)
    const int part  = tid >> 5;                // 0..7   (warp == part: uniform)
    const int gq0   = blockIdx.x * QPB + 2 * qslot;
    const int b     = (blockIdx.x * QPB) >> 13;   // batch (QPB divides Nn)

    float  qx[2], qy[2], qz[2], qqv[2];
    float2 c2x[2], c2y[2], c2z[2], qq2[2];
#pragma unroll
    for (int j = 0; j < 2; j++) {
        int gq = gq0 + j;
        float x = pts[3 * gq + 0];
        float y = pts[3 * gq + 1];
        float z = pts[3 * gq + 2];
        qx[j] = x; qy[j] = y; qz[j] = z;
        qqv[j] = __fadd_rn(__fadd_rn(__fmul_rn(x, x), __fmul_rn(y, y)),
                           __fmul_rn(z, z));
        c2x[j] = make_float2(-2.f * x, -2.f * x);
        c2y[j] = make_float2(-2.f * y, -2.f * y);
        c2z[j] = make_float2(-2.f * z, -2.f * z);
        qq2[j] = make_float2(qqv[j], qqv[j]);
    }

    float pred = 0.f;                          // meaningful for tid < QPB only
    float t[2][3], f[2][3];

    const float *sx[3] = { g2x + b * M2, g3x + b * M3, g4x + b * M4 };
    const float *sy[3] = { g2y + b * M2, g3y + b * M3, g4y + b * M4 };
    const float *sz[3] = { g2z + b * M2, g3z + b * M3, g4z + b * M4 };
    const float *sw[3] = { g2w + b * M2, g3w + b * M3, g4w + b * M4 };
    const float *sf[3] = { g2f + b * M2, g3f + b * M3, g4f + b * M4 };
    const int    sM[3] = { M2, M3, M4 };

#pragma unroll 1
    for (int s = 0; s < 3; s++) {
        scan_set(sx[s], sy[s], sz[s], sw[s], sf[s], sM[s],
                 c2x, c2y, c2z, qq2, tid, part, s_x, s_y, s_z, s_w, s_fv, t, f);
#pragma unroll
        for (int j = 0; j < 2; j++) {
            int q = 2 * qslot + j;
            int bse = (q * PARTS + part) * 3;
            s_m[bse + 0] = make_float2(t[j][0], f[j][0]);
            s_m[bse + 1] = make_float2(t[j][1], f[j][1]);
            s_m[bse + 2] = make_float2(t[j][2], f[j][2]);
        }
        __syncthreads();
        if (tid < QPB) pred += merge_one(s_m + tid * PARTS * 3);
        __syncthreads();
    }

    bool found[2];
    scan_mask(gmx + b * MM, gmy + b * MM, gmz + b * MM, gmw + b * MM, MM,
              c2x, c2y, c2z, qx, qy, qz, qqv, tid, part,
              s_x, s_y, s_z, s_w, found);

    float* s_fl = reinterpret_cast<float*>(s_m);
    s_fl[(2 * qslot + 0) * PARTS + part] = found[0] ? 1.f : 0.f;
    s_fl[(2 * qslot + 1) * PARTS + part] = found[1] ? 1.f : 0.f;
    __syncthreads();
    if (tid < QPB) {
        float fl = 0.f;
#pragma unroll
        for (int k = 0; k < PARTS; k++) fl = fmaxf(fl, s_fl[tid * PARTS + k]);
        int gq = blockIdx.x * QPB + tid;
        out[gq] = pred;                        // pred_hm (B,N,1)
        out[Bn * Nn + gq] = fl;                // gt_hm   (B,N)
    }
}

// ---------------- launch ----------------------------------------------------
extern "C" void kernel_launch(void* const* d_in, const int* in_sizes, int n_in,
                              void* d_out, int out_size) {
    (void)in_sizes; (void)n_in; (void)out_size;
    const float* pts    = (const float*)d_in[0];
    const float* known2 = (const float*)d_in[1];
    const float* feats2 = (const float*)d_in[2];
    const float* known3 = (const float*)d_in[3];
    const float* feats3 = (const float*)d_in[4];
    const float* known4 = (const float*)d_in[5];
    const float* feats4 = (const float*)d_in[6];
    const float* matchp = (const float*)d_in[7];
    const float* w_fc   = (const float*)d_in[8];
    const float* w_cls  = (const float*)d_in[9];
    float* out = (float*)d_out;

    compute_v_kernel<<<1, 96>>>(w_fc, w_cls);
    pack_feat_kernel<<<(Bn * M2 + 255) / 256, 256>>>(known2, feats2, Bn * M2, 0);
    pack_feat_kernel<<<(Bn * M3 + 255) / 256, 256>>>(known3, feats3, Bn * M3, 1);
    pack_feat_kernel<<<(Bn * M4 + 255) / 256, 256>>>(known4, feats4, Bn * M4, 2);
    pack_match_kernel<<<(Bn * MM + 255) / 256, 256>>>(matchp, Bn * MM);
    fused_kernel<<<(Bn * Nn) / QPB, NT>>>(pts, out);
}